// round 16
// baseline (speedup 1.0000x reference)
#include <cuda_runtime.h>
#include <cuda_fp16.h>

#define NN 100000
#define EE 1600000
#define DD 64
#define SCAN_T 1024
#define SCAN_B 98                  // ceil(NN/1024)
#define EDGE_B8 782                // ceil(EE/2048): 8 edges/thread blocks
#define SN_BLOCKS 391              // ceil(NN/256)
#define NWARPS2 (NN / 2)           // 50000 exact: 2 nodes per warp

// ---------------- scratch (static device globals; zero-init at load) --------
// Invariants at entry: g_deg, g_scanstate, g_smaxkey are ZERO.
// True at load; restored by k_scatter every run (graph replays full sequence).
__device__ unsigned g_smaxkey;
__device__ float    g_snode[NN];             // score, then exp(s-gmax) in-place
__device__ float    g_has[NN];
__device__ int      g_deg[NN];
__device__ int      g_off[NN + 1];
__device__ int      g_cur[NN];
__device__ __align__(16) int2 g_rc[EE];      // interleaved (row, col)
__device__ int2     g_edge[EE];              // CSR-by-dest: (srcRow, bits(w))
__device__ __half2  g_xh[(size_t)NN * 32];   // fp16 mirror of x
__device__ float    g_agg[(size_t)NN * DD];
__device__ unsigned long long g_scanstate[SCAN_B];  // (flag<<32)|value

// ---------------- packed f32x2 FMA (2x fp32 FMA rate on sm_103a) ------------
union F2U { float2 f2; unsigned long long u; };
__device__ __forceinline__ F2U ffma2(F2U a, F2U b, F2U c) {
    F2U d;
    asm("fma.rn.f32x2 %0, %1, %2, %3;" : "=l"(d.u) : "l"(a.u), "l"(b.u), "l"(c.u));
    return d;
}

// ---------------- K1: FUSED (edges, 8 consec/thread) || (scores + fp16) -----
__global__ void __launch_bounds__(256) k_fused(
    const float* __restrict__ x, const void* __restrict__ ei,
    const float* __restrict__ Wm, const float* __restrict__ bm) {
    int b = blockIdx.x;
    int t = threadIdx.x;
    if (b < EDGE_B8) {
        // int64 detection: leading odd 32-bit words all zero <=> int64 ids.
        int2 probe = __ldg(&((const int2*)ei)[t]);
        int any = __syncthreads_or(probe.y);
        int e0 = b * 2048 + t * 8;   // 8 consecutive edges per thread
        int row[8], col[8];
        bool full = (e0 + 8 <= EE);
        if (any == 0) {  // int64
            const long long* p = (const long long*)ei;
            if (full) {
#pragma unroll
                for (int k = 0; k < 4; k++) {
                    longlong2 r = __ldg((const longlong2*)(p + e0 + 2 * k));
                    row[2 * k] = (int)r.x; row[2 * k + 1] = (int)r.y;
                    longlong2 c = __ldg((const longlong2*)(p + EE + e0 + 2 * k));
                    col[2 * k] = (int)c.x; col[2 * k + 1] = (int)c.y;
                }
            } else {
#pragma unroll
                for (int k = 0; k < 8; k++) {
                    int e = e0 + k;
                    if (e < EE) { row[k] = (int)__ldg(&p[e]); col[k] = (int)__ldg(&p[(long long)EE + e]); }
                }
            }
        } else {         // int32
            const int* p = (const int*)ei;
            if (full) {
#pragma unroll
                for (int k = 0; k < 2; k++) {
                    int4 r = __ldg((const int4*)(p + e0 + 4 * k));
                    row[4 * k] = r.x; row[4 * k + 1] = r.y; row[4 * k + 2] = r.z; row[4 * k + 3] = r.w;
                    int4 c = __ldg((const int4*)(p + EE + e0 + 4 * k));
                    col[4 * k] = c.x; col[4 * k + 1] = c.y; col[4 * k + 2] = c.z; col[4 * k + 3] = c.w;
                }
            } else {
#pragma unroll
                for (int k = 0; k < 8; k++) {
                    int e = e0 + k;
                    if (e < EE) { row[k] = __ldg(&p[e]); col[k] = __ldg(&p[EE + e]); }
                }
            }
        }
        if (full) {
#pragma unroll
            for (int k = 0; k < 4; k++) {
                int4 v = make_int4(row[2 * k], col[2 * k], row[2 * k + 1], col[2 * k + 1]);
                *(int4*)&g_rc[e0 + 2 * k] = v;
            }
#pragma unroll
            for (int k = 0; k < 8; k++) atomicAdd(&g_deg[col[k]], 1);
        } else {
#pragma unroll
            for (int k = 0; k < 8; k++) {
                int e = e0 + k;
                if (e < EE) {
                    g_rc[e] = make_int2(row[k], col[k]);
                    atomicAdd(&g_deg[col[k]], 1);
                }
            }
        }
    } else {
        // ---- per-node score s = x[n].wbar + bmean ----
        __shared__ float swb[DD];
        __shared__ float sbm;
        if (t < DD) {
            float s = 0.f;
#pragma unroll
            for (int j = 0; j < DD; j++) s += __ldg(&Wm[t * DD + j]);
            swb[t] = s * (1.0f / DD);
        }
        if (t == 0) {
            float bs = 0.f;
            for (int j = 0; j < DD; j++) bs += __ldg(&bm[j]);
            sbm = bs * (1.0f / DD);
        }
        __syncthreads();
        int n0 = (b - EDGE_B8) * 256;
        int n = n0 + t;
        float s = -1e30f;
        if (n < NN) {
            const float4* xp = (const float4*)(x + (size_t)n * DD);
            float acc = 0.f;
#pragma unroll
            for (int i = 0; i < DD / 4; i++) {
                float4 v = __ldg(&xp[i]);
                acc += v.x * swb[4 * i] + v.y * swb[4 * i + 1] +
                       v.z * swb[4 * i + 2] + v.w * swb[4 * i + 3];
            }
            s = acc + sbm;  // BETA = 1.0
            g_snode[n] = s;
        }
        float m = s;
#pragma unroll
        for (int o = 16; o; o >>= 1) m = fmaxf(m, __shfl_xor_sync(0xffffffffu, m, o));
        if ((t & 31) == 0) {
            unsigned bb = __float_as_uint(m);
            unsigned key = (bb & 0x80000000u) ? ~bb : (bb | 0x80000000u);
            atomicMax(&g_smaxkey, key);
        }
        // ---- fp16 mirror, coalesced ----
        int lim = (NN - n0 < 256) ? (NN - n0) : 256;
        for (int j = t; j < lim * 32; j += 256) {
            int node = n0 + (j >> 5);
            int h = j & 31;
            float2 v = __ldg((const float2*)(x + (size_t)node * DD + 2 * h));
            g_xh[(size_t)node * 32 + h] = __floats2half2_rn(v.x, v.y);
        }
    }
}

// ---------------- K2: decoupled-lookback scan + snode -> exp(s-gmax) --------
__global__ void __launch_bounds__(SCAN_T) k_scan() {
    cudaGridDependencySynchronize();  // PDL: wait for k_fused results
    int b = blockIdx.x, t = threadIdx.x;
    int i = b * SCAN_T + t;
    int v = (i < NN) ? g_deg[i] : 0;

    if (i < NN) {
        unsigned k = g_smaxkey;
        unsigned bb = (k & 0x80000000u) ? (k ^ 0x80000000u) : ~k;
        float smax = __uint_as_float(bb);
        g_snode[i] = __expf(g_snode[i] - smax);
    }

    int lane = t & 31, wid = t >> 5;
    int inc = v;
#pragma unroll
    for (int o = 1; o < 32; o <<= 1) {
        int u = __shfl_up_sync(0xffffffffu, inc, o);
        if (lane >= o) inc += u;
    }
    __shared__ int wtot[32];
    __shared__ int stotal;
    __shared__ int sprefix;
    if (lane == 31) wtot[wid] = inc;
    __syncthreads();
    if (wid == 0) {
        int s = wtot[lane];
        int sinc = s;
#pragma unroll
        for (int o = 1; o < 32; o <<= 1) {
            int u = __shfl_up_sync(0xffffffffu, sinc, o);
            if (lane >= o) sinc += u;
        }
        wtot[lane] = sinc - s;
        if (lane == 31) stotal = sinc;
    }
    __syncthreads();
    int ex = wtot[wid] + inc - v;
    int total = stotal;

    if (t == 0) {
        if (b == 0) {
            atomicExch(&g_scanstate[0], (2ull << 32) | (unsigned)total);
            sprefix = 0;
        } else {
            atomicExch(&g_scanstate[b], (1ull << 32) | (unsigned)total);
            int prefix = 0;
            for (int j = b - 1; j >= 0;) {
                unsigned long long st;
                do { st = atomicAdd(&g_scanstate[j], 0ull); } while ((st >> 32) == 0ull);
                prefix += (int)(unsigned)st;
                if ((st >> 32) == 2ull) break;
                j--;
            }
            atomicExch(&g_scanstate[b], (2ull << 32) | (unsigned)(prefix + total));
            sprefix = prefix;
        }
    }
    __syncthreads();
    int off = sprefix + ex;
    if (i < NN) { g_off[i] = off; g_cur[i] = off; }
    if (b == SCAN_B - 1 && t == 0) g_off[NN] = sprefix + total;  // == EE
    cudaTriggerProgrammaticLaunchCompletion();
}

// ---------------- K3: scatter (srcRow, w) into CSR-by-dest + cleanup --------
__global__ void __launch_bounds__(256) k_scatter() {
    cudaGridDependencySynchronize();  // PDL: wait for k_scan results
    int e0 = blockIdx.x * 2048 + threadIdx.x * 8;  // 8 consecutive edges
    if (e0 + 8 <= EE) {
        int2 rc[8];
#pragma unroll
        for (int k = 0; k < 4; k++) {
            int4 v = __ldg((const int4*)&g_rc[e0 + 2 * k]);
            rc[2 * k] = make_int2(v.x, v.y);
            rc[2 * k + 1] = make_int2(v.z, v.w);
        }
        float w[8];
#pragma unroll
        for (int k = 0; k < 8; k++) w[k] = __ldg(&g_snode[rc[k].x]);
#pragma unroll
        for (int k = 0; k < 8; k++) {
            int pos = atomicAdd(&g_cur[rc[k].y], 1);
            g_edge[pos] = make_int2(rc[k].x, __float_as_int(w[k]));
        }
    } else {
#pragma unroll
        for (int k = 0; k < 8; k++) {
            int e = e0 + k;
            if (e < EE) {
                int2 rc = __ldg(&g_rc[e]);
                float w = __ldg(&g_snode[rc.x]);
                int pos = atomicAdd(&g_cur[rc.y], 1);
                g_edge[pos] = make_int2(rc.x, __float_as_int(w));
            }
        }
    }
    // restore zero-invariants for the next graph replay
    int gtid = blockIdx.x * 256 + threadIdx.x;
    for (int i = gtid; i < NN; i += EDGE_B8 * 256) g_deg[i] = 0;
    if (gtid < SCAN_B) g_scanstate[gtid] = 0ull;
    if (gtid == 0) g_smaxkey = 0u;
}

// ---------------- K4: aggregation — 2 nodes/warp x 2 edge-slots x 8 lanes ---
// lane = node*16 + slot*8 + q. Lane owns dims 8q..8q+7 (one fp16 LDG.128 per
// edge). 2 independent gather chains per node; combine slots with xor-8.
__global__ void __launch_bounds__(256) k_agg() {
    cudaGridDependencySynchronize();  // PDL: wait for k_scatter results
    int wi = (blockIdx.x * blockDim.x + threadIdx.x) >> 5;  // warp id
    int lane = threadIdx.x & 31;
    if (wi >= NWARPS2) return;
    int nd = lane >> 4;          // node slot (0..1)
    int slot = (lane >> 3) & 1;  // edge slot (0..1)
    int q = lane & 7;            // dim octet
    int n = wi * 2 + nd;
    int beg = g_off[n], end = g_off[n + 1];

    F2U a0, a1, a2, a3;
    a0.u = a1.u = a2.u = a3.u = 0ull;
    float sumw = 0.f;
#pragma unroll 2
    for (int i = beg + slot; i < end; i += 2) {
        int2 ed = __ldg(&g_edge[i]);
        float w = __int_as_float(ed.y);
        sumw += w;
        uint4 hv = __ldg((const uint4*)(g_xh + (size_t)ed.x * 32 + q * 4));
        F2U wp; wp.f2 = make_float2(w, w);
        F2U f0, f1, f2, f3;
        f0.f2 = __half22float2(*(__half2*)&hv.x);
        f1.f2 = __half22float2(*(__half2*)&hv.y);
        f2.f2 = __half22float2(*(__half2*)&hv.z);
        f3.f2 = __half22float2(*(__half2*)&hv.w);
        a0 = ffma2(wp, f0, a0);
        a1 = ffma2(wp, f1, a1);
        a2 = ffma2(wp, f2, a2);
        a3 = ffma2(wp, f3, a3);
    }
    // combine the two edge slots (xor 8 stays within the same node's 16 lanes)
    a0.f2.x += __shfl_xor_sync(0xffffffffu, a0.f2.x, 8);
    a0.f2.y += __shfl_xor_sync(0xffffffffu, a0.f2.y, 8);
    a1.f2.x += __shfl_xor_sync(0xffffffffu, a1.f2.x, 8);
    a1.f2.y += __shfl_xor_sync(0xffffffffu, a1.f2.y, 8);
    a2.f2.x += __shfl_xor_sync(0xffffffffu, a2.f2.x, 8);
    a2.f2.y += __shfl_xor_sync(0xffffffffu, a2.f2.y, 8);
    a3.f2.x += __shfl_xor_sync(0xffffffffu, a3.f2.x, 8);
    a3.f2.y += __shfl_xor_sync(0xffffffffu, a3.f2.y, 8);
    sumw += __shfl_xor_sync(0xffffffffu, sumw, 8);

    float inv = (sumw > 0.f) ? (1.0f / sumw) : 0.f;
    if (slot == 0) {
        float* op = g_agg + (size_t)n * DD + q * 8;
        *(float4*)op = make_float4(a0.f2.x * inv, a0.f2.y * inv,
                                   a1.f2.x * inv, a1.f2.y * inv);
        *(float4*)(op + 4) = make_float4(a2.f2.x * inv, a2.f2.y * inv,
                                         a3.f2.x * inv, a3.f2.y * inv);
        if (q == 0) g_has[n] = (sumw > 0.f) ? 1.0f : 0.0f;
    }
}

// ---------------- K5: out = agg@Wm + has*bm + x@Wr + br ---------------------
#define SA_STRIDE 260
__global__ void __launch_bounds__(256, 1) k_out(
    const float* __restrict__ x,
    const float* __restrict__ Wm, const float* __restrict__ bm,
    const float* __restrict__ Wr, const float* __restrict__ br,
    float* __restrict__ out) {
    cudaGridDependencySynchronize();  // PDL: wait for k_agg results
    __shared__ float sAk[32 * SA_STRIDE];  // [k within chunk][node]
    __shared__ float sWs[32 * 64];         // [k within chunk][col]

    int t = threadIdx.x;
    int cg = t & 7;
    int ng = t >> 3;
    int nb0 = blockIdx.x * 256;

    float4 bm0 = __ldg((const float4*)(bm + cg * 8));
    float4 bm1 = __ldg((const float4*)(bm + cg * 8 + 4));
    float4 br0 = __ldg((const float4*)(br + cg * 8));
    float4 br1 = __ldg((const float4*)(br + cg * 8 + 4));

    F2U acc[8][4];
#pragma unroll
    for (int i = 0; i < 8; i++)
#pragma unroll
        for (int p = 0; p < 4; p++) acc[i][p].u = 0ull;

    int node = nb0 + t;
    for (int kc = 0; kc < 4; kc++) {
        const float* Asrc = (kc < 2) ? g_agg : x;
        int koff = (kc < 2) ? kc * 32 : (kc - 2) * 32;
        const float* Wsrc = (kc < 2) ? (Wm + kc * 32 * 64) : (Wr + (kc - 2) * 32 * 64);
        __syncthreads();
        const float4* ap = (const float4*)(Asrc + (size_t)node * DD + koff);
#pragma unroll
        for (int kq = 0; kq < 8; kq++) {
            float4 v = (node < NN) ? __ldg(&ap[kq]) : make_float4(0.f, 0.f, 0.f, 0.f);
            sAk[(kq * 4 + 0) * SA_STRIDE + t] = v.x;
            sAk[(kq * 4 + 1) * SA_STRIDE + t] = v.y;
            sAk[(kq * 4 + 2) * SA_STRIDE + t] = v.z;
            sAk[(kq * 4 + 3) * SA_STRIDE + t] = v.w;
        }
        ((float4*)sWs)[t] = __ldg(&((const float4*)Wsrc)[t]);
        ((float4*)sWs)[t + 256] = __ldg(&((const float4*)Wsrc)[t + 256]);
        __syncthreads();

#pragma unroll 4
        for (int kk = 0; kk < 32; kk++) {
            float4 wa = *(const float4*)&sWs[kk * 64 + cg * 8];
            float4 wb = *(const float4*)&sWs[kk * 64 + cg * 8 + 4];
            F2U w0, w1, w2, w3;
            w0.f2 = make_float2(wa.x, wa.y); w1.f2 = make_float2(wa.z, wa.w);
            w2.f2 = make_float2(wb.x, wb.y); w3.f2 = make_float2(wb.z, wb.w);
            float4 a03 = *(const float4*)&sAk[kk * SA_STRIDE + ng * 8];
            float4 a47 = *(const float4*)&sAk[kk * SA_STRIDE + ng * 8 + 4];
            float av[8] = {a03.x, a03.y, a03.z, a03.w, a47.x, a47.y, a47.z, a47.w};
#pragma unroll
            for (int i = 0; i < 8; i++) {
                F2U ap2; ap2.f2 = make_float2(av[i], av[i]);
                acc[i][0] = ffma2(ap2, w0, acc[i][0]);
                acc[i][1] = ffma2(ap2, w1, acc[i][1]);
                acc[i][2] = ffma2(ap2, w2, acc[i][2]);
                acc[i][3] = ffma2(ap2, w3, acc[i][3]);
            }
        }
    }

#pragma unroll
    for (int i = 0; i < 8; i++) {
        int n = nb0 + ng * 8 + i;
        if (n >= NN) break;
        float h = g_has[n];
        float4 o0 = make_float4(acc[i][0].f2.x + h * bm0.x + br0.x,
                                acc[i][0].f2.y + h * bm0.y + br0.y,
                                acc[i][1].f2.x + h * bm0.z + br0.z,
                                acc[i][1].f2.y + h * bm0.w + br0.w);
        float4 o1 = make_float4(acc[i][2].f2.x + h * bm1.x + br1.x,
                                acc[i][2].f2.y + h * bm1.y + br1.y,
                                acc[i][3].f2.x + h * bm1.z + br1.z,
                                acc[i][3].f2.y + h * bm1.w + br1.w);
        float* op = out + (size_t)n * DD + cg * 8;
        *(float4*)op = o0;
        *(float4*)(op + 4) = o1;
    }
}

// ---------------- launcher (PDL-chained dependent launches) ------------------
template <typename F, typename... Args>
static void launch_pdl(F func, dim3 grid, dim3 block, Args... args) {
    cudaLaunchConfig_t cfg = {};
    cfg.gridDim = grid;
    cfg.blockDim = block;
    cudaLaunchAttribute attr[1];
    attr[0].id = cudaLaunchAttributeProgrammaticStreamSerialization;
    attr[0].val.programmaticStreamSerializationAllowed = 1;
    cfg.attrs = attr;
    cfg.numAttrs = 1;
    cudaLaunchKernelEx(&cfg, func, args...);
}

extern "C" void kernel_launch(void* const* d_in, const int* in_sizes, int n_in,
                              void* d_out, int out_size) {
    const float* x  = (const float*)d_in[0];
    const void*  ei = d_in[1];
    const float* Wm = (const float*)d_in[2];
    const float* bm = (const float*)d_in[3];
    const float* Wr = (const float*)d_in[4];
    const float* br = (const float*)d_in[5];
    float* out = (float*)d_out;

    k_fused<<<EDGE_B8 + SN_BLOCKS, 256>>>(x, ei, Wm, bm);
    launch_pdl(k_scan, dim3(SCAN_B), dim3(SCAN_T));
    launch_pdl(k_scatter, dim3(EDGE_B8), dim3(256));
    launch_pdl(k_agg, dim3((NWARPS2 * 32 + 255) / 256), dim3(256));
    launch_pdl(k_out, dim3(SN_BLOCKS), dim3(256), x, Wm, bm, Wr, br, out);
}

// round 17
// speedup vs baseline: 1.0268x; 1.0268x over previous
#include <cuda_runtime.h>
#include <cuda_fp16.h>

#define NN 100000
#define EE 1600000
#define DD 64
#define SCAN_T 1024
#define SCAN_B 98                  // ceil(NN/1024)
#define EDGE_B8 782                // ceil(EE/2048): 8 edges/thread blocks
#define SN_BLOCKS 391              // ceil(NN/256)
#define NGROUPS (NN / 4)           // 25000 exact: 4 nodes per warp

// ---------------- scratch (static device globals; zero-init at load) --------
// Invariants at entry: g_deg, g_scanstate, g_smaxkey are ZERO.
// True at load; restored by k_scatter every run (graph replays full sequence).
__device__ unsigned g_smaxkey;
__device__ float    g_snode[NN];             // score, then exp(s-gmax) in-place
__device__ float    g_has[NN];
__device__ int      g_deg[NN];
__device__ int      g_off[NN + 1];
__device__ int      g_cur[NN];
__device__ int2     g_rc[EE];                // interleaved (row, col)
__device__ int2     g_edge[EE];              // CSR-by-dest: (srcRow, bits(w))
__device__ __half2  g_xh[(size_t)NN * 32];   // fp16 mirror of x
__device__ __half2  g_aggh[(size_t)NN * 32]; // fp16 aggregated features
__device__ unsigned long long g_scanstate[SCAN_B];  // (flag<<32)|value

// ---------------- packed f32x2 FMA (2x fp32 FMA rate on sm_103a) ------------
union F2U { float2 f2; unsigned long long u; };
__device__ __forceinline__ F2U ffma2(F2U a, F2U b, F2U c) {
    F2U d;
    asm("fma.rn.f32x2 %0, %1, %2, %3;" : "=l"(d.u) : "l"(a.u), "l"(b.u), "l"(c.u));
    return d;
}

// ---------------- K1: FUSED (edges, 8/thread) || (scores + fp16 copy) -------
__global__ void __launch_bounds__(256) k_fused(
    const float* __restrict__ x, const void* __restrict__ ei,
    const float* __restrict__ Wm, const float* __restrict__ bm) {
    int b = blockIdx.x;
    int t = threadIdx.x;
    if (b < EDGE_B8) {
        // int64 detection: leading odd 32-bit words all zero <=> int64 ids.
        int2 probe = __ldg(&((const int2*)ei)[t]);
        int any = __syncthreads_or(probe.y);
        int e0 = b * 2048 + t;
        int row[8], col[8];
        if (any == 0) {  // int64
            const long long* p = (const long long*)ei;
#pragma unroll
            for (int k = 0; k < 8; k++) {
                int e = e0 + k * 256;
                if (e < EE) {
                    row[k] = (int)__ldg(&p[e]);
                    col[k] = (int)__ldg(&p[(long long)EE + e]);
                }
            }
        } else {         // int32
            const int* p = (const int*)ei;
#pragma unroll
            for (int k = 0; k < 8; k++) {
                int e = e0 + k * 256;
                if (e < EE) {
                    row[k] = __ldg(&p[e]);
                    col[k] = __ldg(&p[EE + e]);
                }
            }
        }
#pragma unroll
        for (int k = 0; k < 8; k++) {
            int e = e0 + k * 256;
            if (e < EE) {
                g_rc[e] = make_int2(row[k], col[k]);
                atomicAdd(&g_deg[col[k]], 1);
            }
        }
    } else {
        // ---- per-node score s = x[n].wbar + bmean ----
        __shared__ float swb[DD];
        __shared__ float sbm;
        if (t < DD) {
            float s = 0.f;
#pragma unroll
            for (int j = 0; j < DD; j++) s += __ldg(&Wm[t * DD + j]);
            swb[t] = s * (1.0f / DD);
        }
        if (t == 0) {
            float bs = 0.f;
            for (int j = 0; j < DD; j++) bs += __ldg(&bm[j]);
            sbm = bs * (1.0f / DD);
        }
        __syncthreads();
        int n0 = (b - EDGE_B8) * 256;
        int n = n0 + t;
        float s = -1e30f;
        if (n < NN) {
            const float4* xp = (const float4*)(x + (size_t)n * DD);
            float acc = 0.f;
#pragma unroll
            for (int i = 0; i < DD / 4; i++) {
                float4 v = __ldg(&xp[i]);
                acc += v.x * swb[4 * i] + v.y * swb[4 * i + 1] +
                       v.z * swb[4 * i + 2] + v.w * swb[4 * i + 3];
            }
            s = acc + sbm;  // BETA = 1.0
            g_snode[n] = s;
        }
        float m = s;
#pragma unroll
        for (int o = 16; o; o >>= 1) m = fmaxf(m, __shfl_xor_sync(0xffffffffu, m, o));
        if ((t & 31) == 0) {
            unsigned bb = __float_as_uint(m);
            unsigned key = (bb & 0x80000000u) ? ~bb : (bb | 0x80000000u);
            atomicMax(&g_smaxkey, key);
        }
        // ---- fp16 mirror, coalesced ----
        int lim = (NN - n0 < 256) ? (NN - n0) : 256;
        for (int j = t; j < lim * 32; j += 256) {
            int node = n0 + (j >> 5);
            int h = j & 31;
            float2 v = __ldg((const float2*)(x + (size_t)node * DD + 2 * h));
            g_xh[(size_t)node * 32 + h] = __floats2half2_rn(v.x, v.y);
        }
    }
}

// ---------------- K2: decoupled-lookback scan + snode -> exp(s-gmax) --------
__global__ void __launch_bounds__(SCAN_T) k_scan() {
    cudaGridDependencySynchronize();  // PDL: wait for k_fused results
    int b = blockIdx.x, t = threadIdx.x;
    int i = b * SCAN_T + t;
    int v = (i < NN) ? g_deg[i] : 0;

    if (i < NN) {
        unsigned k = g_smaxkey;
        unsigned bb = (k & 0x80000000u) ? (k ^ 0x80000000u) : ~k;
        float smax = __uint_as_float(bb);
        g_snode[i] = __expf(g_snode[i] - smax);
    }

    int lane = t & 31, wid = t >> 5;
    int inc = v;
#pragma unroll
    for (int o = 1; o < 32; o <<= 1) {
        int u = __shfl_up_sync(0xffffffffu, inc, o);
        if (lane >= o) inc += u;
    }
    __shared__ int wtot[32];
    __shared__ int stotal;
    __shared__ int sprefix;
    if (lane == 31) wtot[wid] = inc;
    __syncthreads();
    if (wid == 0) {
        int s = wtot[lane];
        int sinc = s;
#pragma unroll
        for (int o = 1; o < 32; o <<= 1) {
            int u = __shfl_up_sync(0xffffffffu, sinc, o);
            if (lane >= o) sinc += u;
        }
        wtot[lane] = sinc - s;
        if (lane == 31) stotal = sinc;
    }
    __syncthreads();
    int ex = wtot[wid] + inc - v;
    int total = stotal;

    if (t == 0) {
        if (b == 0) {
            atomicExch(&g_scanstate[0], (2ull << 32) | (unsigned)total);
            sprefix = 0;
        } else {
            atomicExch(&g_scanstate[b], (1ull << 32) | (unsigned)total);
            int prefix = 0;
            for (int j = b - 1; j >= 0;) {
                unsigned long long st;
                do { st = atomicAdd(&g_scanstate[j], 0ull); } while ((st >> 32) == 0ull);
                prefix += (int)(unsigned)st;
                if ((st >> 32) == 2ull) break;
                j--;
            }
            atomicExch(&g_scanstate[b], (2ull << 32) | (unsigned)(prefix + total));
            sprefix = prefix;
        }
    }
    __syncthreads();
    int off = sprefix + ex;
    if (i < NN) { g_off[i] = off; g_cur[i] = off; }
    if (b == SCAN_B - 1 && t == 0) g_off[NN] = sprefix + total;  // == EE
    cudaTriggerProgrammaticLaunchCompletion();
}

// ---------------- K3: scatter (srcRow, w) into CSR-by-dest + cleanup --------
__global__ void __launch_bounds__(256) k_scatter() {
    cudaGridDependencySynchronize();  // PDL: wait for k_scan results
    int e0 = blockIdx.x * 2048 + threadIdx.x;
#pragma unroll
    for (int k = 0; k < 8; k++) {
        int e = e0 + k * 256;
        if (e < EE) {
            int2 rc = __ldg(&g_rc[e]);
            float w = __ldg(&g_snode[rc.x]);
            int pos = atomicAdd(&g_cur[rc.y], 1);
            g_edge[pos] = make_int2(rc.x, __float_as_int(w));
        }
    }
    // restore zero-invariants for the next graph replay
    int gtid = blockIdx.x * 256 + threadIdx.x;
    for (int i = gtid; i < NN; i += EDGE_B8 * 256) g_deg[i] = 0;
    if (gtid < SCAN_B) g_scanstate[gtid] = 0ull;
    if (gtid == 0) g_smaxkey = 0u;
}

// ---------------- K4: aggregation — 8 lanes/node, 4 nodes/warp, no shuffles -
// Lane owns dims 8q..8q+7 (one fp16 LDG.128 per edge). Edge record carries
// (row, w). Output stored fp16 (one 16B store per lane).
__global__ void __launch_bounds__(256) k_agg() {
    cudaGridDependencySynchronize();  // PDL: wait for k_scatter results
    int wi = (blockIdx.x * blockDim.x + threadIdx.x) >> 5;  // warp id
    int lane = threadIdx.x & 31;
    if (wi >= NGROUPS) return;
    int g = lane >> 3;   // node slot within warp
    int q = lane & 7;    // dim octet
    int n = wi * 4 + g;
    int beg = g_off[n], end = g_off[n + 1];

    F2U a0, a1, a2, a3;
    a0.u = a1.u = a2.u = a3.u = 0ull;
    float sumw = 0.f;
#pragma unroll 2
    for (int i = beg; i < end; i++) {
        int2 ed = __ldg(&g_edge[i]);
        float w = __int_as_float(ed.y);
        sumw += w;
        uint4 hv = __ldg((const uint4*)(g_xh + (size_t)ed.x * 32 + q * 4));
        F2U wp; wp.f2 = make_float2(w, w);
        F2U f0, f1, f2, f3;
        f0.f2 = __half22float2(*(__half2*)&hv.x);
        f1.f2 = __half22float2(*(__half2*)&hv.y);
        f2.f2 = __half22float2(*(__half2*)&hv.z);
        f3.f2 = __half22float2(*(__half2*)&hv.w);
        a0 = ffma2(wp, f0, a0);
        a1 = ffma2(wp, f1, a1);
        a2 = ffma2(wp, f2, a2);
        a3 = ffma2(wp, f3, a3);
    }
    float inv = (sumw > 0.f) ? (1.0f / sumw) : 0.f;
    uint4 hv;
    *(__half2*)&hv.x = __floats2half2_rn(a0.f2.x * inv, a0.f2.y * inv);
    *(__half2*)&hv.y = __floats2half2_rn(a1.f2.x * inv, a1.f2.y * inv);
    *(__half2*)&hv.z = __floats2half2_rn(a2.f2.x * inv, a2.f2.y * inv);
    *(__half2*)&hv.w = __floats2half2_rn(a3.f2.x * inv, a3.f2.y * inv);
    *(uint4*)(g_aggh + (size_t)n * 32 + q * 4) = hv;
    if (q == 0) g_has[n] = (sumw > 0.f) ? 1.0f : 0.0f;
}

// ---------------- K5: out = agg@Wm + has*bm + x@Wr + br ---------------------
#define SA_STRIDE 260
__global__ void __launch_bounds__(256, 1) k_out(
    const float* __restrict__ x,
    const float* __restrict__ Wm, const float* __restrict__ bm,
    const float* __restrict__ Wr, const float* __restrict__ br,
    float* __restrict__ out) {
    cudaGridDependencySynchronize();  // PDL: wait for k_agg results
    __shared__ float sAk[32 * SA_STRIDE];  // [k within chunk][node]
    __shared__ float sWs[32 * 64];         // [k within chunk][col]

    int t = threadIdx.x;
    int cg = t & 7;
    int ng = t >> 3;
    int nb0 = blockIdx.x * 256;

    float4 bm0 = __ldg((const float4*)(bm + cg * 8));
    float4 bm1 = __ldg((const float4*)(bm + cg * 8 + 4));
    float4 br0 = __ldg((const float4*)(br + cg * 8));
    float4 br1 = __ldg((const float4*)(br + cg * 8 + 4));

    F2U acc[8][4];
#pragma unroll
    for (int i = 0; i < 8; i++)
#pragma unroll
        for (int p = 0; p < 4; p++) acc[i][p].u = 0ull;

    int node = nb0 + t;
    for (int kc = 0; kc < 4; kc++) {
        int koff = (kc < 2) ? kc * 32 : (kc - 2) * 32;
        const float* Wsrc = (kc < 2) ? (Wm + kc * 32 * 64) : (Wr + (kc - 2) * 32 * 64);
        __syncthreads();
        if (kc < 2) {
            // stage fp16 agg chunk: 4 x LDG.128 = 32 halfs, convert to fp32
            const uint4* ahp = (const uint4*)(g_aggh + (size_t)node * 32 + koff / 2);
#pragma unroll
            for (int kq = 0; kq < 4; kq++) {
                uint4 hv = (node < NN) ? __ldg(&ahp[kq]) : make_uint4(0, 0, 0, 0);
                float2 f0 = __half22float2(*(__half2*)&hv.x);
                float2 f1 = __half22float2(*(__half2*)&hv.y);
                float2 f2 = __half22float2(*(__half2*)&hv.z);
                float2 f3 = __half22float2(*(__half2*)&hv.w);
                sAk[(kq * 8 + 0) * SA_STRIDE + t] = f0.x;
                sAk[(kq * 8 + 1) * SA_STRIDE + t] = f0.y;
                sAk[(kq * 8 + 2) * SA_STRIDE + t] = f1.x;
                sAk[(kq * 8 + 3) * SA_STRIDE + t] = f1.y;
                sAk[(kq * 8 + 4) * SA_STRIDE + t] = f2.x;
                sAk[(kq * 8 + 5) * SA_STRIDE + t] = f2.y;
                sAk[(kq * 8 + 6) * SA_STRIDE + t] = f3.x;
                sAk[(kq * 8 + 7) * SA_STRIDE + t] = f3.y;
            }
        } else {
            const float4* ap = (const float4*)(x + (size_t)node * DD + koff);
#pragma unroll
            for (int kq = 0; kq < 8; kq++) {
                float4 v = (node < NN) ? __ldg(&ap[kq]) : make_float4(0.f, 0.f, 0.f, 0.f);
                sAk[(kq * 4 + 0) * SA_STRIDE + t] = v.x;
                sAk[(kq * 4 + 1) * SA_STRIDE + t] = v.y;
                sAk[(kq * 4 + 2) * SA_STRIDE + t] = v.z;
                sAk[(kq * 4 + 3) * SA_STRIDE + t] = v.w;
            }
        }
        ((float4*)sWs)[t] = __ldg(&((const float4*)Wsrc)[t]);
        ((float4*)sWs)[t + 256] = __ldg(&((const float4*)Wsrc)[t + 256]);
        __syncthreads();

#pragma unroll 4
        for (int kk = 0; kk < 32; kk++) {
            float4 wa = *(const float4*)&sWs[kk * 64 + cg * 8];
            float4 wb = *(const float4*)&sWs[kk * 64 + cg * 8 + 4];
            F2U w0, w1, w2, w3;
            w0.f2 = make_float2(wa.x, wa.y); w1.f2 = make_float2(wa.z, wa.w);
            w2.f2 = make_float2(wb.x, wb.y); w3.f2 = make_float2(wb.z, wb.w);
            float4 a03 = *(const float4*)&sAk[kk * SA_STRIDE + ng * 8];
            float4 a47 = *(const float4*)&sAk[kk * SA_STRIDE + ng * 8 + 4];
            float av[8] = {a03.x, a03.y, a03.z, a03.w, a47.x, a47.y, a47.z, a47.w};
#pragma unroll
            for (int i = 0; i < 8; i++) {
                F2U ap2; ap2.f2 = make_float2(av[i], av[i]);
                acc[i][0] = ffma2(ap2, w0, acc[i][0]);
                acc[i][1] = ffma2(ap2, w1, acc[i][1]);
                acc[i][2] = ffma2(ap2, w2, acc[i][2]);
                acc[i][3] = ffma2(ap2, w3, acc[i][3]);
            }
        }
    }

#pragma unroll
    for (int i = 0; i < 8; i++) {
        int n = nb0 + ng * 8 + i;
        if (n >= NN) break;
        float h = g_has[n];
        float4 o0 = make_float4(acc[i][0].f2.x + h * bm0.x + br0.x,
                                acc[i][0].f2.y + h * bm0.y + br0.y,
                                acc[i][1].f2.x + h * bm0.z + br0.z,
                                acc[i][1].f2.y + h * bm0.w + br0.w);
        float4 o1 = make_float4(acc[i][2].f2.x + h * bm1.x + br1.x,
                                acc[i][2].f2.y + h * bm1.y + br1.y,
                                acc[i][3].f2.x + h * bm1.z + br1.z,
                                acc[i][3].f2.y + h * bm1.w + br1.w);
        float* op = out + (size_t)n * DD + cg * 8;
        *(float4*)op = o0;
        *(float4*)(op + 4) = o1;
    }
}

// ---------------- launcher (PDL-chained dependent launches) ------------------
template <typename F, typename... Args>
static void launch_pdl(F func, dim3 grid, dim3 block, Args... args) {
    cudaLaunchConfig_t cfg = {};
    cfg.gridDim = grid;
    cfg.blockDim = block;
    cudaLaunchAttribute attr[1];
    attr[0].id = cudaLaunchAttributeProgrammaticStreamSerialization;
    attr[0].val.programmaticStreamSerializationAllowed = 1;
    cfg.attrs = attr;
    cfg.numAttrs = 1;
    cudaLaunchKernelEx(&cfg, func, args...);
}

extern "C" void kernel_launch(void* const* d_in, const int* in_sizes, int n_in,
                              void* d_out, int out_size) {
    const float* x  = (const float*)d_in[0];
    const void*  ei = d_in[1];
    const float* Wm = (const float*)d_in[2];
    const float* bm = (const float*)d_in[3];
    const float* Wr = (const float*)d_in[4];
    const float* br = (const float*)d_in[5];
    float* out = (float*)d_out;

    k_fused<<<EDGE_B8 + SN_BLOCKS, 256>>>(x, ei, Wm, bm);
    launch_pdl(k_scan, dim3(SCAN_B), dim3(SCAN_T));
    launch_pdl(k_scatter, dim3(EDGE_B8), dim3(256));
    launch_pdl(k_agg, dim3((NGROUPS * 32 + 255) / 256), dim3(256));
    launch_pdl(k_out, dim3(SN_BLOCKS), dim3(256), x, Wm, bm, Wr, br, out);
}